// round 1
// baseline (speedup 1.0000x reference)
#include <cuda_runtime.h>
#include <cuda_bf16.h>
#include <cstdint>

#define NN 100000
#define EE 1600000
#define HH 128
#define LL 4
#define GG 256
#define CC 10

// ---------------- scratch (static device globals; no allocation) ----------------
__device__ float g_hA[NN * HH];        // 51.2 MB
__device__ float g_hT[NN * HH];        // 51.2 MB
__device__ int   g_deg[NN];
__device__ float g_dinv[NN];
__device__ int   g_offs[NN + 1];
__device__ int   g_cursor[NN];
__device__ int   g_col[EE];
__device__ float g_w[EE];
__device__ int   g_part[512];
__device__ int   g_starts[GG + 1];
__device__ float g_scale[(LL + 1) * HH];
__device__ float g_bias[(LL + 1) * HH];

// ---------------- small helpers ----------------
__device__ __forceinline__ unsigned long long pack_dup(float x) {
    unsigned long long r;
    asm("mov.b64 %0, {%1, %1};" : "=l"(r) : "f"(x));
    return r;
}
__device__ __forceinline__ float2 ffma2(float2 d, unsigned long long a, float2 b) {
    unsigned long long dd, bb;
    dd = *reinterpret_cast<unsigned long long*>(&d);
    bb = *reinterpret_cast<unsigned long long*>(&b);
    asm("fma.rn.f32x2 %0, %1, %2, %0;" : "+l"(dd) : "l"(a), "l"(bb));
    return *reinterpret_cast<float2*>(&dd);
}

// ---------------- graph preprocessing ----------------
__global__ void k_zero_deg() {
    int i = blockIdx.x * blockDim.x + threadIdx.x;
    if (i < NN) g_deg[i] = 0;
}
__global__ void k_count(const int* __restrict__ dst) {
    int e = blockIdx.x * blockDim.x + threadIdx.x;
    if (e < EE) atomicAdd(&g_deg[dst[e]], 1);
}
__global__ void k_dinv() {
    int i = blockIdx.x * blockDim.x + threadIdx.x;
    if (i < NN) g_dinv[i] = rsqrtf((float)g_deg[i] + 1.0f);
}
// per-block exclusive scan of degrees
__global__ void k_scan1() {
    __shared__ int s[256];
    int t = threadIdx.x;
    int i = blockIdx.x * 256 + t;
    int v = (i < NN) ? g_deg[i] : 0;
    s[t] = v;
    __syncthreads();
    #pragma unroll
    for (int off = 1; off < 256; off <<= 1) {
        int x = (t >= off) ? s[t - off] : 0;
        __syncthreads();
        s[t] += x;
        __syncthreads();
    }
    if (i < NN) g_offs[i] = s[t] - v;        // exclusive within block
    if (t == 255) g_part[blockIdx.x] = s[255];
}
__global__ void k_scan2() {                   // 1 block, 512 threads over 391 partials
    __shared__ int s[512];
    int t = threadIdx.x;
    int v = (t < 391) ? g_part[t] : 0;
    s[t] = v;
    __syncthreads();
    #pragma unroll
    for (int off = 1; off < 512; off <<= 1) {
        int x = (t >= off) ? s[t - off] : 0;
        __syncthreads();
        s[t] += x;
        __syncthreads();
    }
    if (t < 391) g_part[t] = s[t] - v;        // exclusive
}
__global__ void k_scan3() {
    int i = blockIdx.x * blockDim.x + threadIdx.x;
    if (i < NN) {
        int o = g_offs[i] + g_part[blockIdx.x * 256 / 256 == 0 ? 0 : 0];  // placeholder (overwritten below)
        o = g_offs[i] + g_part[(blockIdx.x * blockDim.x + threadIdx.x) >> 8];
        g_offs[i] = o;
        g_cursor[i] = o;
    }
    if (i == 0) g_offs[NN] = EE;
}
__global__ void k_fill(const int* __restrict__ src, const int* __restrict__ dst) {
    int e = blockIdx.x * blockDim.x + threadIdx.x;
    if (e < EE) {
        int s = src[e], d = dst[e];
        int p = atomicAdd(&g_cursor[d], 1);
        g_col[p] = s;
        g_w[p] = g_dinv[s] * g_dinv[d];
    }
}
// fold BN into per-channel scale/bias per stage (stage 0 = input proj)
__global__ void k_prep(const float* __restrict__ b_in, const float* __restrict__ gam,
                       const float* __restrict__ bet, const float* __restrict__ rm,
                       const float* __restrict__ rv, const float* __restrict__ bs) {
    int t = threadIdx.x;
    if (t < HH) {
        g_scale[t] = 1.0f;
        g_bias[t]  = b_in[t];
        for (int l = 0; l < LL; l++) {
            float s = gam[l * HH + t] * rsqrtf(rv[l * HH + t] + 1e-5f);
            g_scale[(l + 1) * HH + t] = s;
            g_bias[(l + 1) * HH + t]  = (bs[l * HH + t] - rm[l * HH + t]) * s + bet[l * HH + t];
        }
    }
}
__global__ void k_starts(const int* __restrict__ batch) {
    int t = threadIdx.x;
    if (t <= GG) {
        int lo = 0, hi = NN;
        while (lo < hi) {
            int m = (lo + hi) >> 1;
            if (batch[m] < t) lo = m + 1; else hi = m;
        }
        g_starts[t] = lo;
    }
}

// ---------------- SpMM: out = (A_norm + diag(dinv^2)) @ hin ----------------
__global__ void k_spmm(const float4* __restrict__ hin, float4* __restrict__ hout) {
    int warp = (blockIdx.x * blockDim.x + threadIdx.x) >> 5;
    int lane = threadIdx.x & 31;
    if (warp >= NN) return;
    float di = g_dinv[warp];
    float sw = di * di;
    float4 acc = hin[warp * 32 + lane];
    acc.x *= sw; acc.y *= sw; acc.z *= sw; acc.w *= sw;
    int s = g_offs[warp], e = g_offs[warp + 1];
    int j = s;
    // unrolled by 2 for a bit of MLP
    for (; j + 1 < e; j += 2) {
        float w0 = g_w[j];     int c0 = g_col[j];
        float w1 = g_w[j + 1]; int c1 = g_col[j + 1];
        float4 v0 = hin[c0 * 32 + lane];
        float4 v1 = hin[c1 * 32 + lane];
        acc.x += w0 * v0.x; acc.y += w0 * v0.y; acc.z += w0 * v0.z; acc.w += w0 * v0.w;
        acc.x += w1 * v1.x; acc.y += w1 * v1.y; acc.z += w1 * v1.z; acc.w += w1 * v1.w;
    }
    if (j < e) {
        float w0 = g_w[j]; int c0 = g_col[j];
        float4 v0 = hin[c0 * 32 + lane];
        acc.x += w0 * v0.x; acc.y += w0 * v0.y; acc.z += w0 * v0.z; acc.w += w0 * v0.w;
    }
    hout[warp * 32 + lane] = acc;
}

// ---------------- GEMM: C = relu(A[M,128] @ B[128,128] * scale + bias) ----------------
// 64-row tiles, 256 threads, f32x2 packed FFMA. Dynamic smem: 64*132 + 128*128 floats.
#define GEMM_SMEM ((64 * 132 + 128 * 128) * 4)
__global__ void k_gemm(const float* __restrict__ A, const float* __restrict__ B,
                       float* __restrict__ Cc, int M, int stage) {
    extern __shared__ float sm[];
    float (*As)[132] = (float (*)[132])sm;
    float (*Bs)[128] = (float (*)[128])(sm + 64 * 132);
    int tid = threadIdx.x;
    int rb = blockIdx.x * 64;

    // load B (128x128) to smem
    const float4* B4 = (const float4*)B;
    float4* Bs4 = (float4*)Bs;
    #pragma unroll
    for (int i = tid; i < 4096; i += 256) Bs4[i] = B4[i];
    // load A tile (64x128), zero-pad OOB rows
    #pragma unroll
    for (int i = tid; i < 2048; i += 256) {
        int r = i >> 5, c = i & 31;
        float4 v = make_float4(0.f, 0.f, 0.f, 0.f);
        if (rb + r < M) v = ((const float4*)A)[(size_t)(rb + r) * 32 + c];
        *(float4*)&As[r][c * 4] = v;
    }
    __syncthreads();

    int tx = tid & 15, ty = tid >> 4;   // cols tx*8..+7, rows ty+16*i
    float2 acc[4][4];
    #pragma unroll
    for (int i = 0; i < 4; i++)
        #pragma unroll
        for (int j = 0; j < 4; j++) acc[i][j] = make_float2(0.f, 0.f);

    #pragma unroll 4
    for (int k = 0; k < 128; k++) {
        unsigned long long a2[4];
        #pragma unroll
        for (int i = 0; i < 4; i++) a2[i] = pack_dup(As[ty + 16 * i][k]);
        float4 b0 = *(const float4*)&Bs[k][tx * 8];
        float4 b1 = *(const float4*)&Bs[k][tx * 8 + 4];
        float2 bb[4];
        bb[0] = make_float2(b0.x, b0.y); bb[1] = make_float2(b0.z, b0.w);
        bb[2] = make_float2(b1.x, b1.y); bb[3] = make_float2(b1.z, b1.w);
        #pragma unroll
        for (int i = 0; i < 4; i++)
            #pragma unroll
            for (int j = 0; j < 4; j++) acc[i][j] = ffma2(acc[i][j], a2[i], bb[j]);
    }

    const float* sc = g_scale + stage * HH;
    const float* bi = g_bias + stage * HH;
    #pragma unroll
    for (int i = 0; i < 4; i++) {
        int row = rb + ty + 16 * i;
        if (row >= M) continue;
        #pragma unroll
        for (int j = 0; j < 4; j++) {
            int c0 = tx * 8 + 2 * j;
            float2 o;
            o.x = fmaxf(acc[i][j].x * sc[c0]     + bi[c0],     0.0f);
            o.y = fmaxf(acc[i][j].y * sc[c0 + 1] + bi[c0 + 1], 0.0f);
            *(float2*)&Cc[(size_t)row * 128 + c0] = o;
        }
    }
}

// ---------------- pool + MLP head ----------------
__global__ void k_head(const float* __restrict__ h,
                       const float* __restrict__ fc1w, const float* __restrict__ fc1b,
                       const float* __restrict__ fc2w, const float* __restrict__ fc2b,
                       float* __restrict__ out) {
    __shared__ float ge[128];
    __shared__ float hid[64];
    int g = blockIdx.x, t = threadIdx.x;   // 128 threads
    int s = g_starts[g], e = g_starts[g + 1];
    float sum = 0.f;
    for (int r = s; r < e; r++) sum += h[(size_t)r * 128 + t];
    float cnt = (float)(e - s);
    ge[t] = sum / fmaxf(cnt, 1.0f);
    __syncthreads();
    if (t < 64) {
        float a = fc1b[t];
        #pragma unroll 8
        for (int k = 0; k < 128; k++) a += ge[k] * fc1w[k * 64 + t];
        hid[t] = fmaxf(a, 0.0f);
    }
    __syncthreads();
    if (t < 10) {
        float a = fc2b[t];
        #pragma unroll 8
        for (int k = 0; k < 64; k++) a += hid[k] * fc2w[k * 10 + t];
        out[g * 10 + t] = a;
    }
}

// ---------------- launch ----------------
extern "C" void kernel_launch(void* const* d_in, const int* in_sizes, int n_in,
                              void* d_out, int out_size) {
    const float* x      = (const float*)d_in[0];
    const int*   ei     = (const int*)d_in[1];
    const int*   src    = ei;
    const int*   dst    = ei + EE;
    const int*   batch  = (const int*)d_in[2];
    const float* W_in   = (const float*)d_in[3];
    const float* b_in   = (const float*)d_in[4];
    const float* Ws     = (const float*)d_in[5];
    const float* bs     = (const float*)d_in[6];
    const float* gammas = (const float*)d_in[7];
    const float* betas  = (const float*)d_in[8];
    const float* rmeans = (const float*)d_in[9];
    const float* rvars  = (const float*)d_in[10];
    const float* fc1_w  = (const float*)d_in[11];
    const float* fc1_b  = (const float*)d_in[12];
    const float* fc2_w  = (const float*)d_in[13];
    const float* fc2_b  = (const float*)d_in[14];
    float* out = (float*)d_out;

    cudaFuncSetAttribute(k_gemm, cudaFuncAttributeMaxDynamicSharedMemorySize, GEMM_SMEM);

    float *hA, *hT;
    cudaGetSymbolAddress((void**)&hA, g_hA);
    cudaGetSymbolAddress((void**)&hT, g_hT);

    const int NB = (NN + 255) / 256;      // 391
    const int EB = (EE + 255) / 256;      // 6250

    // CSR build
    k_zero_deg<<<NB, 256>>>();
    k_count<<<EB, 256>>>(dst);
    k_dinv<<<NB, 256>>>();
    k_scan1<<<NB, 256>>>();
    k_scan2<<<1, 512>>>();
    k_scan3<<<NB, 256>>>();
    k_fill<<<EB, 256>>>(src, dst);
    k_prep<<<1, 128>>>(b_in, gammas, betas, rmeans, rvars, bs);
    k_starts<<<1, 257>>>(batch);

    const int GB = (NN + 63) / 64;        // 1563 gemm blocks
    const int SB = (NN * 32 + 255) / 256; // 12500 spmm blocks

    // input projection
    k_gemm<<<GB, 256, GEMM_SMEM>>>(x, W_in, hA, NN, 0);

    // 4 GCN layers: aggregate, then GEMM with fused BN+bias+ReLU
    for (int l = 0; l < LL; l++) {
        k_spmm<<<SB, 256>>>((const float4*)hA, (float4*)hT);
        k_gemm<<<GB, 256, GEMM_SMEM>>>(hT, Ws + (size_t)l * HH * HH, hA, NN, l + 1);
    }

    // pool + head
    k_head<<<GG, 128>>>(hA, fc1_w, fc1_b, fc2_w, fc2_b, out);
}

// round 2
// speedup vs baseline: 2.1642x; 2.1642x over previous
#include <cuda_runtime.h>
#include <cuda_bf16.h>
#include <cstdint>

#define NN 100000
#define EE 1600000
#define HH 128
#define LL 4
#define GG 256
#define CC 10

// ---------------- scratch (static device globals; no allocation) ----------------
__device__ float g_hA[NN * HH];        // 51.2 MB
__device__ float g_hT[NN * HH];        // 51.2 MB
__device__ int   g_deg[NN];
__device__ float g_dinv[NN];
__device__ int   g_offs[NN + 1];
__device__ int   g_cursor[NN];
__device__ int   g_col[EE];
__device__ float g_w[EE];
__device__ int   g_part[512];
__device__ int   g_starts[GG + 1];
__device__ float g_scale[(LL + 1) * HH];
__device__ float g_bias[(LL + 1) * HH];

// ---------------- graph preprocessing ----------------
__global__ void k_zero_deg() {
    int i = blockIdx.x * blockDim.x + threadIdx.x;
    if (i < NN) g_deg[i] = 0;
}
__global__ void k_count(const int* __restrict__ dst) {
    int e = blockIdx.x * blockDim.x + threadIdx.x;
    if (e < EE) atomicAdd(&g_deg[dst[e]], 1);
}
__global__ void k_dinv() {
    int i = blockIdx.x * blockDim.x + threadIdx.x;
    if (i < NN) g_dinv[i] = rsqrtf((float)g_deg[i] + 1.0f);
}
__global__ void k_scan1() {
    __shared__ int s[256];
    int t = threadIdx.x;
    int i = blockIdx.x * 256 + t;
    int v = (i < NN) ? g_deg[i] : 0;
    s[t] = v;
    __syncthreads();
    #pragma unroll
    for (int off = 1; off < 256; off <<= 1) {
        int x = (t >= off) ? s[t - off] : 0;
        __syncthreads();
        s[t] += x;
        __syncthreads();
    }
    if (i < NN) g_offs[i] = s[t] - v;
    if (t == 255) g_part[blockIdx.x] = s[255];
}
__global__ void k_scan2() {
    __shared__ int s[512];
    int t = threadIdx.x;
    int v = (t < 391) ? g_part[t] : 0;
    s[t] = v;
    __syncthreads();
    #pragma unroll
    for (int off = 1; off < 512; off <<= 1) {
        int x = (t >= off) ? s[t - off] : 0;
        __syncthreads();
        s[t] += x;
        __syncthreads();
    }
    if (t < 391) g_part[t] = s[t] - v;
}
__global__ void k_scan3() {
    int i = blockIdx.x * blockDim.x + threadIdx.x;
    if (i < NN) {
        int o = g_offs[i] + g_part[i >> 8];
        g_offs[i] = o;
        g_cursor[i] = o;
    }
    if (i == 0) g_offs[NN] = EE;
}
__global__ void k_fill(const int* __restrict__ src, const int* __restrict__ dst) {
    int e = blockIdx.x * blockDim.x + threadIdx.x;
    if (e < EE) {
        int s = src[e], d = dst[e];
        int p = atomicAdd(&g_cursor[d], 1);
        g_col[p] = s;
        g_w[p] = g_dinv[s] * g_dinv[d];
    }
}
__global__ void k_prep(const float* __restrict__ b_in, const float* __restrict__ gam,
                       const float* __restrict__ bet, const float* __restrict__ rm,
                       const float* __restrict__ rv, const float* __restrict__ bs) {
    int t = threadIdx.x;
    if (t < HH) {
        g_scale[t] = 1.0f;
        g_bias[t]  = b_in[t];
        for (int l = 0; l < LL; l++) {
            float s = gam[l * HH + t] * rsqrtf(rv[l * HH + t] + 1e-5f);
            g_scale[(l + 1) * HH + t] = s;
            g_bias[(l + 1) * HH + t]  = (bs[l * HH + t] - rm[l * HH + t]) * s + bet[l * HH + t];
        }
    }
}
__global__ void k_starts(const int* __restrict__ batch) {
    int t = threadIdx.x;
    if (t <= GG) {
        int lo = 0, hi = NN;
        while (lo < hi) {
            int m = (lo + hi) >> 1;
            if (batch[m] < t) lo = m + 1; else hi = m;
        }
        g_starts[t] = lo;
    }
}

// ---------------- SpMM: out = (A_norm + diag(dinv^2)) @ hin ----------------
__global__ void k_spmm(const float4* __restrict__ hin, float4* __restrict__ hout) {
    int warp = (blockIdx.x * blockDim.x + threadIdx.x) >> 5;
    int lane = threadIdx.x & 31;
    if (warp >= NN) return;
    float di = g_dinv[warp];
    float sw = di * di;
    float4 acc = hin[warp * 32 + lane];
    acc.x *= sw; acc.y *= sw; acc.z *= sw; acc.w *= sw;
    int s = g_offs[warp], e = g_offs[warp + 1];
    int j = s;
    for (; j + 3 < e; j += 4) {
        float w0 = g_w[j];     int c0 = g_col[j];
        float w1 = g_w[j + 1]; int c1 = g_col[j + 1];
        float w2 = g_w[j + 2]; int c2 = g_col[j + 2];
        float w3 = g_w[j + 3]; int c3 = g_col[j + 3];
        float4 v0 = hin[c0 * 32 + lane];
        float4 v1 = hin[c1 * 32 + lane];
        float4 v2 = hin[c2 * 32 + lane];
        float4 v3 = hin[c3 * 32 + lane];
        acc.x += w0 * v0.x; acc.y += w0 * v0.y; acc.z += w0 * v0.z; acc.w += w0 * v0.w;
        acc.x += w1 * v1.x; acc.y += w1 * v1.y; acc.z += w1 * v1.z; acc.w += w1 * v1.w;
        acc.x += w2 * v2.x; acc.y += w2 * v2.y; acc.z += w2 * v2.z; acc.w += w2 * v2.w;
        acc.x += w3 * v3.x; acc.y += w3 * v3.y; acc.z += w3 * v3.z; acc.w += w3 * v3.w;
    }
    for (; j < e; j++) {
        float w0 = g_w[j]; int c0 = g_col[j];
        float4 v0 = hin[c0 * 32 + lane];
        acc.x += w0 * v0.x; acc.y += w0 * v0.y; acc.z += w0 * v0.z; acc.w += w0 * v0.w;
    }
    hout[warp * 32 + lane] = acc;
}

// ---------------- GEMM (TF32 tensor core): C = relu((A @ B) * scale + bias) ----------------
// A: [M,128] row-major, B: [128,128] row-major (k-major). 64-row tiles, 8 warps.
// Each warp computes a 32x32 tile via mma.sync.m16n8k8.tf32.
#define APAD 4
#define BPAD 8
#define AS_W (HH + APAD)            // 132
#define BS_W (HH + BPAD)            // 136
#define GEMM_SMEM ((64 * AS_W + 128 * BS_W) * 4)

__device__ __forceinline__ void mma_tf32(float& c0, float& c1, float& c2, float& c3,
                                         uint32_t a0, uint32_t a1, uint32_t a2, uint32_t a3,
                                         uint32_t b0, uint32_t b1) {
    asm volatile(
        "mma.sync.aligned.m16n8k8.row.col.f32.tf32.tf32.f32 "
        "{%0,%1,%2,%3}, {%4,%5,%6,%7}, {%8,%9}, {%0,%1,%2,%3};\n"
        : "+f"(c0), "+f"(c1), "+f"(c2), "+f"(c3)
        : "r"(a0), "r"(a1), "r"(a2), "r"(a3), "r"(b0), "r"(b1));
}

__global__ __launch_bounds__(256, 2)
void k_gemm(const float* __restrict__ A, const float* __restrict__ B,
            float* __restrict__ Cc, int M, int stage) {
    extern __shared__ float sm[];
    float (*As)[AS_W] = (float (*)[AS_W])sm;
    float (*Bs)[BS_W] = (float (*)[BS_W])(sm + 64 * AS_W);
    int tid = threadIdx.x;
    int rb = blockIdx.x * 64;

    // load B (128x128) to smem [k][n] with pad
    const float4* B4 = (const float4*)B;
    #pragma unroll
    for (int i = tid; i < 4096; i += 256) {
        int r = i >> 5, c = i & 31;
        *(float4*)&Bs[r][c * 4] = B4[i];
    }
    // load A tile (64x128), zero-pad OOB rows
    #pragma unroll
    for (int i = tid; i < 2048; i += 256) {
        int r = i >> 5, c = i & 31;
        float4 v = make_float4(0.f, 0.f, 0.f, 0.f);
        if (rb + r < M) v = ((const float4*)A)[(size_t)(rb + r) * 32 + c];
        *(float4*)&As[r][c * 4] = v;
    }
    __syncthreads();

    int w = tid >> 5;
    int lane = tid & 31;
    int g = lane >> 2, tg = lane & 3;
    int warp_m = (w >> 2) * 32;      // 0 or 32
    int warp_n = (w & 3) * 32;       // 0,32,64,96

    // acc[mt][nt][4]
    float acc[2][4][4];
    #pragma unroll
    for (int mt = 0; mt < 2; mt++)
        #pragma unroll
        for (int nt = 0; nt < 4; nt++)
            #pragma unroll
            for (int q = 0; q < 4; q++) acc[mt][nt][q] = 0.f;

    #pragma unroll 4
    for (int kk = 0; kk < 16; kk++) {
        int k0 = kk * 8;
        uint32_t a[2][4], b[4][2];
        #pragma unroll
        for (int mt = 0; mt < 2; mt++) {
            int r = warp_m + 16 * mt + g;
            a[mt][0] = __float_as_uint(As[r][k0 + tg]);
            a[mt][1] = __float_as_uint(As[r + 8][k0 + tg]);
            a[mt][2] = __float_as_uint(As[r][k0 + tg + 4]);
            a[mt][3] = __float_as_uint(As[r + 8][k0 + tg + 4]);
        }
        #pragma unroll
        for (int nt = 0; nt < 4; nt++) {
            int cc = warp_n + 8 * nt + g;
            b[nt][0] = __float_as_uint(Bs[k0 + tg][cc]);
            b[nt][1] = __float_as_uint(Bs[k0 + tg + 4][cc]);
        }
        #pragma unroll
        for (int mt = 0; mt < 2; mt++)
            #pragma unroll
            for (int nt = 0; nt < 4; nt++)
                mma_tf32(acc[mt][nt][0], acc[mt][nt][1], acc[mt][nt][2], acc[mt][nt][3],
                         a[mt][0], a[mt][1], a[mt][2], a[mt][3], b[nt][0], b[nt][1]);
    }

    const float* sc = g_scale + stage * HH;
    const float* bi = g_bias + stage * HH;
    #pragma unroll
    for (int mt = 0; mt < 2; mt++) {
        int r0 = rb + warp_m + 16 * mt + g;
        #pragma unroll
        for (int nt = 0; nt < 4; nt++) {
            int c0 = warp_n + 8 * nt + 2 * tg;
            float s0 = sc[c0], s1 = sc[c0 + 1];
            float q0 = bi[c0], q1 = bi[c0 + 1];
            if (r0 < M) {
                float2 o;
                o.x = fmaxf(acc[mt][nt][0] * s0 + q0, 0.0f);
                o.y = fmaxf(acc[mt][nt][1] * s1 + q1, 0.0f);
                *(float2*)&Cc[(size_t)r0 * 128 + c0] = o;
            }
            if (r0 + 8 < M) {
                float2 o;
                o.x = fmaxf(acc[mt][nt][2] * s0 + q0, 0.0f);
                o.y = fmaxf(acc[mt][nt][3] * s1 + q1, 0.0f);
                *(float2*)&Cc[(size_t)(r0 + 8) * 128 + c0] = o;
            }
        }
    }
}

// ---------------- pool + MLP head ----------------
__global__ void k_head(const float* __restrict__ h,
                       const float* __restrict__ fc1w, const float* __restrict__ fc1b,
                       const float* __restrict__ fc2w, const float* __restrict__ fc2b,
                       float* __restrict__ out) {
    __shared__ float ge[128];
    __shared__ float hid[64];
    int g = blockIdx.x, t = threadIdx.x;   // 128 threads
    int s = g_starts[g], e = g_starts[g + 1];
    float sum = 0.f;
    for (int r = s; r < e; r++) sum += h[(size_t)r * 128 + t];
    float cnt = (float)(e - s);
    ge[t] = sum / fmaxf(cnt, 1.0f);
    __syncthreads();
    if (t < 64) {
        float a = fc1b[t];
        #pragma unroll 8
        for (int k = 0; k < 128; k++) a += ge[k] * fc1w[k * 64 + t];
        hid[t] = fmaxf(a, 0.0f);
    }
    __syncthreads();
    if (t < 10) {
        float a = fc2b[t];
        #pragma unroll 8
        for (int k = 0; k < 64; k++) a += hid[k] * fc2w[k * 10 + t];
        out[g * 10 + t] = a;
    }
}

// ---------------- launch ----------------
extern "C" void kernel_launch(void* const* d_in, const int* in_sizes, int n_in,
                              void* d_out, int out_size) {
    const float* x      = (const float*)d_in[0];
    const int*   ei     = (const int*)d_in[1];
    const int*   src    = ei;
    const int*   dst    = ei + EE;
    const int*   batch  = (const int*)d_in[2];
    const float* W_in   = (const float*)d_in[3];
    const float* b_in   = (const float*)d_in[4];
    const float* Ws     = (const float*)d_in[5];
    const float* bs     = (const float*)d_in[6];
    const float* gammas = (const float*)d_in[7];
    const float* betas  = (const float*)d_in[8];
    const float* rmeans = (const float*)d_in[9];
    const float* rvars  = (const float*)d_in[10];
    const float* fc1_w  = (const float*)d_in[11];
    const float* fc1_b  = (const float*)d_in[12];
    const float* fc2_w  = (const float*)d_in[13];
    const float* fc2_b  = (const float*)d_in[14];
    float* out = (float*)d_out;

    cudaFuncSetAttribute(k_gemm, cudaFuncAttributeMaxDynamicSharedMemorySize, GEMM_SMEM);

    float *hA, *hT;
    cudaGetSymbolAddress((void**)&hA, g_hA);
    cudaGetSymbolAddress((void**)&hT, g_hT);

    const int NB = (NN + 255) / 256;      // 391
    const int EB = (EE + 255) / 256;      // 6250

    // CSR build
    k_zero_deg<<<NB, 256>>>();
    k_count<<<EB, 256>>>(dst);
    k_dinv<<<NB, 256>>>();
    k_scan1<<<NB, 256>>>();
    k_scan2<<<1, 512>>>();
    k_scan3<<<NB, 256>>>();
    k_fill<<<EB, 256>>>(src, dst);
    k_prep<<<1, 128>>>(b_in, gammas, betas, rmeans, rvars, bs);
    k_starts<<<1, 257>>>(batch);

    const int GB = (NN + 63) / 64;        // 1563 gemm blocks
    const int SB = (NN * 32 + 255) / 256; // 12500 spmm blocks

    // input projection
    k_gemm<<<GB, 256, GEMM_SMEM>>>(x, W_in, hA, NN, 0);

    // 4 GCN layers: aggregate, then GEMM with fused BN+bias+ReLU
    for (int l = 0; l < LL; l++) {
        k_spmm<<<SB, 256>>>((const float4*)hA, (float4*)hT);
        k_gemm<<<GB, 256, GEMM_SMEM>>>(hT, Ws + (size_t)l * HH * HH, hA, NN, l + 1);
    }

    // pool + head
    k_head<<<GG, 128>>>(hA, fc1_w, fc1_b, fc2_w, fc2_b, out);
}